// round 16
// baseline (speedup 1.0000x reference)
#include <cuda_runtime.h>
#include <cuda_bf16.h>
#include <stdint.h>

#define NPTS 200000
#define DIM 64
#define KC 256
#define BW2 144.0f
#define ITERS 10

#define KB 128
#define PBI 64
#define NTI 3125
#define GXI 148
#define PB 128
#define NT128 1563
#define GXF 148
#define XTS 132
#define XTI 68
#define XRS 68
#define MSS 132
#define NT64 3125
#define SPB 148
#define CCAP 4096

typedef unsigned long long u64p;
#define PK2(d, lo, hi) asm("mov.b64 %0, {%1, %2};" : "=l"(d) : "f"(lo), "f"(hi))
#define UPK2(lo, hi, s) asm("mov.b64 {%0, %1}, %2;" : "=f"(lo), "=f"(hi) : "l"(s))
#define FMA2(d, a, b, c) asm("fma.rn.f32x2 %0, %1, %2, %3;" : "=l"(d) : "l"(a), "l"(b), "l"(c))
#define ADD2(d, a, b) asm("add.rn.f32x2 %0, %1, %2;" : "=l"(d) : "l"(a), "l"(b))

__device__ float g_c[2][KC][DIM];
__device__ float g_acc[KC][DIM];
__device__ float g_cnt[KC];
__device__ double g_sumx[DIM];
__device__ float g_x2[NPTS];
__device__ unsigned long long g_best[KC];
__device__ int g_seed64;
__device__ int g_tileflag[NT64];
__device__ int g_chgA[ITERS];
__device__ unsigned g_barcnt;
__device__ volatile unsigned g_bargen;
__device__ unsigned g_minx2bits;
__device__ int g_ncand;
__device__ int g_cand[CCAP];
__device__ int g_finaldone;

// ------------------------------------------------- prologue kernels

__global__ void detect_kernel(const void* __restrict__ seed) {
    __shared__ int bad;
    if (threadIdx.x == 0) {
        bad = 0;
        g_minx2bits = 0x7f7fffffu;
        g_ncand = 0;
        g_finaldone = 0;
    }
    if (threadIdx.x < DIM) g_sumx[threadIdx.x] = 0.0;
    __syncthreads();
    unsigned long long v = ((const unsigned long long*)seed)[threadIdx.x];
    if (v >= (unsigned long long)NPTS) atomicOr(&bad, 1);
    __syncthreads();
    if (threadIdx.x == 0) g_seed64 = bad ? 0 : 1;
}

__global__ void x2_kernel(const float* __restrict__ x) {
    __shared__ float wsum[8][DIM];
    const int tid = threadIdx.x;
    const int n = blockIdx.x * 256 + tid;
    const int lane = tid & 31, wid = tid >> 5;
    const bool valid = n < NPTS;
    const float4* r = (const float4*)(x + (size_t)n * DIM);

    float x2 = 0.f;
#pragma unroll
    for (int q = 0; q < 16; q++) {
        float4 v = valid ? r[q] : make_float4(0.f, 0.f, 0.f, 0.f);
        x2 = fmaf(v.x, v.x, x2); x2 = fmaf(v.y, v.y, x2);
        x2 = fmaf(v.z, v.z, x2); x2 = fmaf(v.w, v.w, x2);
#pragma unroll
        for (int off = 16; off > 0; off >>= 1) {
            v.x += __shfl_xor_sync(0xffffffffu, v.x, off);
            v.y += __shfl_xor_sync(0xffffffffu, v.y, off);
            v.z += __shfl_xor_sync(0xffffffffu, v.z, off);
            v.w += __shfl_xor_sync(0xffffffffu, v.w, off);
        }
        if (lane == 0) *(float4*)&wsum[wid][4 * q] = v;
    }
    if (valid) g_x2[n] = x2;
    if (n < NT64) g_tileflag[n] = 0;
    if (n < ITERS) g_chgA[n] = 0;
    {
        float m = valid ? x2 : 1e30f;
#pragma unroll
        for (int off = 16; off > 0; off >>= 1)
            m = fminf(m, __shfl_xor_sync(0xffffffffu, m, off));
        if (lane == 0) atomicMin(&g_minx2bits, __float_as_uint(m));
    }
    __syncthreads();
    if (tid < DIM) {
        float tot = 0.f;
#pragma unroll
        for (int w = 0; w < 8; w++) tot += wsum[w][tid];
        atomicAdd(&g_sumx[tid], (double)tot);
    }
}

__global__ void seed_kernel(const float* __restrict__ x, const void* __restrict__ seedraw) {
    int k = blockIdx.x, d = threadIdx.x;
    long long idx;
    if (g_seed64) idx = ((const long long*)seedraw)[k];
    else          idx = (long long)(((const int*)seedraw)[k]);
    g_c[0][k][d] = x[idx * DIM + d];
    g_acc[k][d] = 0.f;
    if (d == 0) { g_cnt[k] = 0.f; g_best[k] = ~0ull; }
}

// ------------------------------------------- dense iteration (it=0)
// Round-14 version verbatim (measured 277us): 128c x 64p tiles, 2 CTAs/SM,
// prefetch pipeline, point-paired FMA2.

__global__ void __launch_bounds__(256, 2) iter_kernel(const float* __restrict__ x, int it) {
    extern __shared__ float smem[];
    float* Cs  = smem;
    float* c2s = Cs + 64 * KB;
    float* Xt  = c2s + KB;
    float* Xr  = Xt + 64 * XTI;
    float* Ms  = Xr + PBI * XRS;
    float* x2s = Ms + PBI * MSS;

    const int tid = threadIdx.x;
    const int ty = tid >> 4, tx = tid & 15;
    const int ck0 = ty * 8, p0 = tx * 4, dq = tx * 4;
    const int kb = blockIdx.y * KB;
    const int ploc = tid & 63, d0 = (tid >> 6) * 16;
    const float* cin = &g_c[it & 1][0][0];

    for (int e = tid; e < KB * DIM; e += 256) {
        int ck = e & (KB - 1), d = e >> 7;
        Cs[d * KB + ck] = cin[(size_t)(kb + ck) * DIM + d];
    }
    __syncthreads();
    if (tid < KB) {
        float s = 0.f;
#pragma unroll
        for (int d = 0; d < DIM; d++) { float c = Cs[d * KB + tid]; s = fmaf(c, c, s); }
        c2s[tid] = s;
    }
    __syncthreads();

    float c2f[8];
#pragma unroll
    for (int i = 0; i < 8; i++) c2f[i] = c2s[ck0 + i];
    u64p neg2; { float m2 = -2.0f; PK2(neg2, m2, m2); }

    u64p acc2[4][4];
#pragma unroll
    for (int i = 0; i < 4; i++)
#pragma unroll
        for (int j = 0; j < 4; j++) acc2[i][j] = 0ull;
    float cnt[8] = {0.f, 0.f, 0.f, 0.f, 0.f, 0.f, 0.f, 0.f};

    float4 pf[4];
    float pfx2 = 0.f;
    {
        const int tb = blockIdx.x * PBI;
        const float4* src = (const float4*)(x + (size_t)(tb + ploc) * DIM + d0);
#pragma unroll
        for (int k = 0; k < 4; k++) pf[k] = src[k];
        if (tid < PBI) pfx2 = g_x2[tb + tid];
    }

    for (int t = blockIdx.x; t < NTI; t += GXI) {
        __syncthreads();
        {
#pragma unroll
            for (int k = 0; k < 4; k++) {
                float4 v = pf[k];
                *(float4*)(Xr + ploc * XRS + d0 + 4 * k) = v;
                Xt[(d0 + 4 * k + 0) * XTI + ploc] = v.x;
                Xt[(d0 + 4 * k + 1) * XTI + ploc] = v.y;
                Xt[(d0 + 4 * k + 2) * XTI + ploc] = v.z;
                Xt[(d0 + 4 * k + 3) * XTI + ploc] = v.w;
            }
            if (tid < PBI) x2s[tid] = pfx2;
        }
        __syncthreads();

        const int tn = t + GXI;
        if (tn < NTI) {
            const int tbn = tn * PBI;
            const float4* src = (const float4*)(x + (size_t)(tbn + ploc) * DIM + d0);
#pragma unroll
            for (int k = 0; k < 4; k++) pf[k] = src[k];
            if (tid < PBI) pfx2 = g_x2[tbn + tid];
        }

        u64p S2[8][2];
#pragma unroll
        for (int i = 0; i < 8; i++) { S2[i][0] = 0ull; S2[i][1] = 0ull; }

#pragma unroll 8
        for (int dd = 0; dd < DIM; dd++) {
            float4 ca = *(const float4*)(Cs + dd * KB + ck0);
            float4 cb = *(const float4*)(Cs + dd * KB + ck0 + 4);
            float4 xa = *(const float4*)(Xt + dd * XTI + p0);
            u64p xp[2];
            PK2(xp[0], xa.x, xa.y); PK2(xp[1], xa.z, xa.w);
            float cv[8] = {ca.x, ca.y, ca.z, ca.w, cb.x, cb.y, cb.z, cb.w};
#pragma unroll
            for (int i = 0; i < 8; i++) {
                u64p cd; PK2(cd, cv[i], cv[i]);
                FMA2(S2[i][0], cd, xp[0], S2[i][0]);
                FMA2(S2[i][1], cd, xp[1], S2[i][1]);
            }
        }

        {
            const int sw = tx & 7;
            const int colA = 4 * ((2 * ty) ^ sw);
            const int colB = 4 * ((2 * ty + 1) ^ sw);
#pragma unroll
            for (int jp = 0; jp < 2; jp++) {
                u64p x2p; PK2(x2p, x2s[p0 + 2 * jp], x2s[p0 + 2 * jp + 1]);
                float mlo[8], mhi[8];
#pragma unroll
                for (int i = 0; i < 8; i++) {
                    u64p c2d; PK2(c2d, c2f[i], c2f[i]);
                    u64p tsum; ADD2(tsum, c2d, x2p);
                    u64p d2;   FMA2(d2, neg2, S2[i][jp], tsum);
                    float dlo, dhi; UPK2(dlo, dhi, d2);
                    mlo[i] = (dlo < BW2) ? 0.f : 1.f;
                    mhi[i] = (dhi < BW2) ? 0.f : 1.f;
                    cnt[i] += mlo[i] + mhi[i];
                }
                int pA = p0 + 2 * jp, pB = pA + 1;
                *(float4*)(Ms + pA * MSS + colA) = make_float4(mlo[0], mlo[1], mlo[2], mlo[3]);
                *(float4*)(Ms + pA * MSS + colB) = make_float4(mlo[4], mlo[5], mlo[6], mlo[7]);
                *(float4*)(Ms + pB * MSS + colA) = make_float4(mhi[0], mhi[1], mhi[2], mhi[3]);
                *(float4*)(Ms + pB * MSS + colB) = make_float4(mhi[4], mhi[5], mhi[6], mhi[7]);
            }
        }
        __syncthreads();

#pragma unroll 4
        for (int p = 0; p < PBI; p++) {
            const int sw2 = (p >> 2) & 7;
            float4 ma = *(const float4*)(Ms + p * MSS + 4 * ((2 * ty) ^ sw2));
            float4 mb = *(const float4*)(Ms + p * MSS + 4 * ((2 * ty + 1) ^ sw2));
            float4 xv = *(const float4*)(Xr + p * XRS + dq);
            u64p mp[4];
            PK2(mp[0], ma.x, ma.y); PK2(mp[1], ma.z, ma.w);
            PK2(mp[2], mb.x, mb.y); PK2(mp[3], mb.z, mb.w);
            u64p xd[4];
            PK2(xd[0], xv.x, xv.x); PK2(xd[1], xv.y, xv.y);
            PK2(xd[2], xv.z, xv.z); PK2(xd[3], xv.w, xv.w);
#pragma unroll
            for (int i2 = 0; i2 < 4; i2++)
#pragma unroll
                for (int j = 0; j < 4; j++) FMA2(acc2[i2][j], mp[i2], xd[j], acc2[i2][j]);
        }
    }

#pragma unroll
    for (int i2 = 0; i2 < 4; i2++)
#pragma unroll
        for (int j = 0; j < 4; j++) {
            float alo, ahi; UPK2(alo, ahi, acc2[i2][j]);
            atomicAdd(&g_acc[kb + ck0 + 2 * i2 + 0][dq + j], alo);
            atomicAdd(&g_acc[kb + ck0 + 2 * i2 + 1][dq + j], ahi);
        }
#pragma unroll
    for (int i = 0; i < 8; i++) {
        float v = cnt[i];
#pragma unroll
        for (int off = 8; off > 0; off >>= 1)
            v += __shfl_down_sync(0xffffffffu, v, off, 16);
        if (tx == 0) atomicAdd(&g_cnt[kb + ck0 + i], v);
    }
}

// ------------------------------------------- persistent sparse iterations
// Fused: update(it=0) at head, iterations 1..9 w/ early exit, sparse final.

static __device__ __forceinline__ void grid_sync() {
    __threadfence();
    __syncthreads();
    if (threadIdx.x == 0) {
        unsigned gen = g_bargen;
        if (atomicAdd(&g_barcnt, 1u) == SPB - 1) {
            g_barcnt = 0;
            __threadfence();
            g_bargen = gen + 1;
        } else {
            while (g_bargen == gen) { __nanosleep(32); }
        }
    }
    __syncthreads();
}

__global__ void __launch_bounds__(256) sparse_all(const float* __restrict__ x) {
    __shared__ float red[KC];
    __shared__ float redB[KC];
    __shared__ unsigned long long rmin[256];
    const int tid = threadIdx.x;
    const int gtid = blockIdx.x * 256 + tid;
    const int stride = SPB * 256;

    // fused update for it=0 (each block owns 2 centers; no cross-block reads)
    {
        int k = -1, d = tid & 63;
        if (tid < 64) k = blockIdx.x;
        else if (tid < 128) { int kk = blockIdx.x + SPB; if (kk < KC) k = kk; }
        if (k >= 0) {
            double cnt = (double)NPTS - (double)g_cnt[k];
            double v = (g_sumx[d] - (double)g_acc[k][d]) / cnt;
            g_c[1][k][d] = (float)v;
            g_acc[k][d] = 0.f;
        }
        __syncthreads();
        if (tid == 0) {
            g_cnt[blockIdx.x] = 0.f;
            int kk = blockIdx.x + SPB;
            if (kk < KC) g_cnt[kk] = 0.f;
        }
        grid_sync();   // c1 + resets visible everywhere
    }

    for (int it = 1; it < ITERS; it++) {
        const float* cc = &g_c[it & 1][0][0];
        {
            const float4* cr = (const float4*)(cc + (size_t)tid * DIM);
            float c2 = 0.f;
#pragma unroll
            for (int q = 0; q < 16; q++) {
                float4 v = cr[q];
                c2 = fmaf(v.x, v.x, c2); c2 = fmaf(v.y, v.y, c2);
                c2 = fmaf(v.z, v.z, c2); c2 = fmaf(v.w, v.w, c2);
            }
            red[tid] = c2;
            __syncthreads();
            for (int s = 128; s > 0; s >>= 1) {
                if (tid < s) red[tid] = fmaxf(red[tid], red[tid + s]);
                __syncthreads();
            }
        }
        const float cmax = sqrtf(red[0]) + 1e-3f;
        __syncthreads();
        float tthr = 12.0f - cmax - 1e-3f;
        const float thr2 = (tthr > 0.f) ? tthr * tthr : -1.0f;

        for (int n = gtid; n < NPTS; n += stride) {
            const float x2 = g_x2[n];
            if (x2 < thr2) continue;
            g_tileflag[n >> 6] = 1;

            float xv[DIM];
            const float4* xr = (const float4*)(x + (size_t)n * DIM);
#pragma unroll
            for (int q = 0; q < 16; q++) {
                float4 v = xr[q];
                xv[4 * q + 0] = v.x; xv[4 * q + 1] = v.y;
                xv[4 * q + 2] = v.z; xv[4 * q + 3] = v.w;
            }
            for (int k = 0; k < KC; k++) {
                const float4* cr = (const float4*)(cc + (size_t)k * DIM);
                float dot = 0.f, c2 = 0.f;
#pragma unroll
                for (int q = 0; q < 16; q++) {
                    float4 cv = cr[q];
                    dot = fmaf(cv.x, xv[4 * q + 0], dot);
                    dot = fmaf(cv.y, xv[4 * q + 1], dot);
                    dot = fmaf(cv.z, xv[4 * q + 2], dot);
                    dot = fmaf(cv.w, xv[4 * q + 3], dot);
                    c2 = fmaf(cv.x, cv.x, c2); c2 = fmaf(cv.y, cv.y, c2);
                    c2 = fmaf(cv.z, cv.z, c2); c2 = fmaf(cv.w, cv.w, c2);
                }
                float d2 = c2 + x2 - 2.f * dot;
                if (!(d2 < BW2)) {
                    atomicAdd(&g_cnt[k], 1.0f);
#pragma unroll
                    for (int d = 0; d < DIM; d++) atomicAdd(&g_acc[k][d], xv[d]);
                }
            }
        }

        grid_sync();

        int diff = 0;
        {
            int k = -1, d = tid & 63;
            if (tid < 64) k = blockIdx.x;
            else if (tid < 128) { int kk = blockIdx.x + SPB; if (kk < KC) k = kk; }
            if (k >= 0) {
                double cnt = (double)NPTS - (double)g_cnt[k];
                double v = (g_sumx[d] - (double)g_acc[k][d]) / cnt;
                float nf = (float)v;
                if (__float_as_uint(nf) != __float_as_uint(g_c[it & 1][k][d])) diff = 1;
                g_c[(it + 1) & 1][k][d] = nf;
                g_acc[k][d] = 0.f;
            }
        }
        if (__syncthreads_or(diff) && tid == 0) atomicOr(&g_chgA[it], 1);
        if (tid == 0) {
            g_cnt[blockIdx.x] = 0.f;
            int kk = blockIdx.x + SPB;
            if (kk < KC) g_cnt[kk] = 0.f;
        }

        grid_sync();

        if (g_chgA[it] == 0) break;
    }

    // ---- fused sparse final argmin ----
    {
        const float4* ca = (const float4*)&g_c[0][tid][0];
        const float4* cb = (const float4*)&g_c[1][tid][0];
        float c2a = 0.f, c2b = 0.f;
#pragma unroll
        for (int q = 0; q < 16; q++) {
            float4 va = ca[q], vb = cb[q];
            c2a = fmaf(va.x, va.x, c2a); c2a = fmaf(va.y, va.y, c2a);
            c2a = fmaf(va.z, va.z, c2a); c2a = fmaf(va.w, va.w, c2a);
            c2b = fmaf(vb.x, vb.x, c2b); c2b = fmaf(vb.y, vb.y, c2b);
            c2b = fmaf(vb.z, vb.z, c2b); c2b = fmaf(vb.w, vb.w, c2b);
        }
        red[tid] = c2a; redB[tid] = c2b;
        __syncthreads();
        for (int s = 128; s > 0; s >>= 1) {
            if (tid < s) {
                red[tid] = fmaxf(red[tid], red[tid + s]);
                redB[tid] = fmaxf(redB[tid], redB[tid + s]);
            }
            __syncthreads();
        }
    }
    const float cmax10 = sqrtf(red[0]) + 1e-3f;
    const float cmax9  = sqrtf(redB[0]) + 1e-3f;
    const float minx   = sqrtf(__uint_as_float(g_minx2bits));
    const float thr    = minx + 2.f * cmax10 + 0.05f;
    const float thr2   = thr * thr;
    const bool valid   = (minx + cmax9 + 0.05f < 12.0f);

    if (valid) {
        for (int n = gtid; n < NPTS; n += stride) {
            if (g_x2[n] <= thr2) {
                int pos = atomicAdd(&g_ncand, 1);
                if (pos < CCAP) g_cand[pos] = n;
            }
        }
    }
    grid_sync();
    const int ncand = g_ncand;
    if (!valid || ncand == 0 || ncand > CCAP) return;

    for (int k = blockIdx.x; k < KC; k += SPB) {
        unsigned long long bk = ~0ull;
        for (int j = tid; j < ncand; j += 256) {
            const int n = g_cand[j];
            const float* xr = x + (size_t)n * DIM;
            const float x2 = g_x2[n];
            const float* c9r  = &g_c[1][k][0];
            const float* c10r = &g_c[0][k][0];
            float dot9 = 0.f, dot10 = 0.f, c29 = 0.f, c210 = 0.f;
            for (int d = 0; d < DIM; d++) {
                float xv = xr[d], v9 = c9r[d], v10 = c10r[d];
                dot9  = fmaf(v9,  xv, dot9);
                dot10 = fmaf(v10, xv, dot10);
                c29   = fmaf(v9,  v9,  c29);
                c210  = fmaf(v10, v10, c210);
            }
            float d9 = fmaf(-2.f, dot9, c29 + x2);
            if (d9 < BW2) {
                float d2 = fmaxf(fmaf(-2.f, dot10, c210 + x2), 0.f);
                unsigned long long key =
                    ((unsigned long long)__float_as_uint(d2) << 32) | (unsigned)n;
                if (key < bk) bk = key;
            }
        }
        rmin[tid] = bk;
        __syncthreads();
        for (int s = 128; s > 0; s >>= 1) {
            if (tid < s && rmin[tid + s] < rmin[tid]) rmin[tid] = rmin[tid + s];
            __syncthreads();
        }
        if (tid == 0 && rmin[0] != ~0ull) atomicMin(&g_best[k], rmin[0]);
        __syncthreads();
    }
    if (blockIdx.x == 0 && tid == 0) g_finaldone = 1;
}

// ------------------------------------------- dense final (fallback only)

__global__ void __launch_bounds__(256, 2) final_kernel(const float* __restrict__ x) {
    if (g_finaldone) return;
    extern __shared__ float sm[];
    float* Ct   = sm;
    float* c210 = Ct + 64 * KB;
    float* Xt   = c210 + KB;
    float* x2s  = Xt + 64 * XTS;

    const int tid = threadIdx.x;
    const int ty = tid >> 4, tx = tid & 15;
    const int ck0 = ty * 8, p0 = tx * 8;
    const int kb = blockIdx.y * KB;

    for (int e = tid; e < KB * DIM; e += 256) {
        int ck = e & (KB - 1), d = e >> 7;
        Ct[d * KB + ck] = g_c[0][kb + ck][d];
    }
    __syncthreads();
    if (tid < KB) {
        float s = 0.f;
#pragma unroll
        for (int d = 0; d < DIM; d++) { float a = Ct[d * KB + tid]; s = fmaf(a, a, s); }
        c210[tid] = s;
    }
    __syncthreads();

    unsigned long long best[8];
#pragma unroll
    for (int i = 0; i < 8; i++) best[i] = ~0ull;

    for (int t = blockIdx.x; t < NT128; t += GXF) {
        const int tb = t * PB;
        __syncthreads();
        {
            int ploc = tid & 127, d0 = (tid >> 7) * 32;
            bool valid = (tb + ploc) < NPTS;
            const float4* src = (const float4*)(x + (size_t)(tb + ploc) * DIM + d0);
#pragma unroll
            for (int k = 0; k < 8; k++) {
                float4 v = valid ? src[k] : make_float4(0.f, 0.f, 0.f, 0.f);
                Xt[(d0 + 4 * k + 0) * XTS + ploc] = v.x;
                Xt[(d0 + 4 * k + 1) * XTS + ploc] = v.y;
                Xt[(d0 + 4 * k + 2) * XTS + ploc] = v.z;
                Xt[(d0 + 4 * k + 3) * XTS + ploc] = v.w;
            }
            if (tid < PB) x2s[tid] = ((tb + tid) < NPTS) ? g_x2[tb + tid] : 0.f;
        }
        __syncthreads();

        u64p S2[8][4];
#pragma unroll
        for (int i = 0; i < 8; i++)
#pragma unroll
            for (int j = 0; j < 4; j++) S2[i][j] = 0ull;

#pragma unroll 8
        for (int dd = 0; dd < DIM; dd++) {
            float4 ca = *(const float4*)(Ct + dd * KB + ck0);
            float4 cb = *(const float4*)(Ct + dd * KB + ck0 + 4);
            float4 xa = *(const float4*)(Xt + dd * XTS + p0);
            float4 xb = *(const float4*)(Xt + dd * XTS + p0 + 4);
            u64p xp[4];
            PK2(xp[0], xa.x, xa.y); PK2(xp[1], xa.z, xa.w);
            PK2(xp[2], xb.x, xb.y); PK2(xp[3], xb.z, xb.w);
            float cv[8] = {ca.x, ca.y, ca.z, ca.w, cb.x, cb.y, cb.z, cb.w};
#pragma unroll
            for (int i = 0; i < 8; i++) {
                u64p cd; PK2(cd, cv[i], cv[i]);
#pragma unroll
                for (int j = 0; j < 4; j++) FMA2(S2[i][j], cd, xp[j], S2[i][j]);
            }
        }

        const int flagged = g_tileflag[2 * t] |
                            ((2 * t + 1 < NT64) ? g_tileflag[2 * t + 1] : 0);

#pragma unroll
        for (int jp = 0; jp < 4; jp++) {
            const int pA = p0 + 2 * jp, pB = pA + 1;
            const float xa2 = x2s[pA], xb2 = x2s[pB];
            const unsigned ia = (unsigned)(tb + pA), ib = (unsigned)(tb + pB);
#pragma unroll
            for (int i = 0; i < 8; i++) {
                float dlo, dhi; UPK2(dlo, dhi, S2[i][jp]);
                const float c2v = c210[ck0 + i];
                bool oka = true, okb = true;
                if (flagged) {
                    const float* c9r = &g_c[1][kb + ck0 + i][0];
                    float d9a = 0.f, d9b = 0.f, c29v = 0.f;
                    for (int dd = 0; dd < DIM; dd++) {
                        float cv9 = c9r[dd];
                        d9a = fmaf(cv9, Xt[dd * XTS + pA], d9a);
                        d9b = fmaf(cv9, Xt[dd * XTS + pB], d9b);
                        c29v = fmaf(cv9, cv9, c29v);
                    }
                    oka = fmaf(-2.f, d9a, c29v + xa2) < BW2;
                    okb = fmaf(-2.f, d9b, c29v + xb2) < BW2;
                }
                if (oka && ia < NPTS) {
                    float d2 = fmaxf(fmaf(-2.f, dlo, c2v + xa2), 0.f);
                    unsigned long long key =
                        ((unsigned long long)__float_as_uint(d2) << 32) | ia;
                    if (key < best[i]) best[i] = key;
                }
                if (okb && ib < NPTS) {
                    float d2 = fmaxf(fmaf(-2.f, dhi, c2v + xb2), 0.f);
                    unsigned long long key =
                        ((unsigned long long)__float_as_uint(d2) << 32) | ib;
                    if (key < best[i]) best[i] = key;
                }
            }
        }
    }

#pragma unroll
    for (int i = 0; i < 8; i++) {
        unsigned long long v = best[i];
#pragma unroll
        for (int off = 8; off > 0; off >>= 1) {
            unsigned long long o = __shfl_down_sync(0xffffffffu, v, off, 16);
            if (o < v) v = o;
        }
        if (tx == 0) atomicMin(&g_best[kb + ck0 + i], v);
    }
}

// ---------------------------------------------------------------- epilogue

__global__ void zero_out(float* out, int n) {
    int i = blockIdx.x * blockDim.x + threadIdx.x;
    if (i < n) out[i] = 0.f;
}

__global__ void finish_kernel(float* __restrict__ out, const float* __restrict__ x,
                              int out_size) {
    int k = blockIdx.x, d = threadIdx.x;
    if (out_size >= KC * DIM)
        out[k * DIM + d] = g_c[0][k][d];
    unsigned long long b = g_best[k];
    unsigned idx = (b == ~0ull) ? 0u : (unsigned)(b & 0xffffffffu);
    if (out_size >= 2 * KC * DIM)
        out[KC * DIM + k * DIM + d] = x[(size_t)idx * DIM + d];
    if (d == 0 && out_size >= 2 * KC * DIM + KC)
        out[2 * KC * DIM + k] = (float)idx;
}

// ---------------------------------------------------------------- launcher

extern "C" void kernel_launch(void* const* d_in, const int* in_sizes, int n_in,
                              void* d_out, int out_size) {
    const float* x = (const float*)d_in[0];
    const void* seed = d_in[1];
    float* out = (float*)d_out;
    (void)in_sizes; (void)n_in;

    const size_t iterSmem = (size_t)(64 * KB + KB + 64 * XTI + PBI * XRS + PBI * MSS + PBI)
                            * sizeof(float);
    const size_t finalSmem = (size_t)(64 * KB + KB + 64 * XTS + PB) * sizeof(float);
    cudaFuncSetAttribute(iter_kernel,  cudaFuncAttributeMaxDynamicSharedMemorySize, (int)iterSmem);
    cudaFuncSetAttribute(final_kernel, cudaFuncAttributeMaxDynamicSharedMemorySize, (int)finalSmem);

    detect_kernel<<<1, 128>>>(seed);
    x2_kernel<<<(NPTS + 255) / 256, 256>>>(x);
    seed_kernel<<<KC, DIM>>>(x, seed);

    iter_kernel<<<dim3(GXI, KC / KB), 256, iterSmem>>>(x, 0);

    sparse_all<<<SPB, 256>>>(x);     // update(it=0) + iterations 1..9 + sparse final

    final_kernel<<<dim3(GXF, KC / KB), 256, finalSmem>>>(x);   // fallback

    // finish_kernel writes every output element when out_size == 33024
    if (out_size > 0 && out_size != 2 * KC * DIM + KC)
        zero_out<<<(out_size + 255) / 256, 256>>>(out, out_size);
    finish_kernel<<<KC, DIM>>>(out, x, out_size);
}

// round 17
// speedup vs baseline: 1.0573x; 1.0573x over previous
#include <cuda_runtime.h>
#include <cuda_bf16.h>
#include <stdint.h>

#define NPTS 200000
#define DIM 64
#define KC 256
#define BW2 144.0f
#define ITERS 10

#define KB 128
#define PBI 64
#define NTI 3125
#define GXI 148
#define PB 128
#define NT128 1563
#define GXF 148
#define XTS 132
#define XTI 68
#define XRS 68
#define MSS 132
#define NT64 3125
#define SPB 148
#define CCAP 4096

typedef unsigned long long u64p;
#define PK2(d, lo, hi) asm("mov.b64 %0, {%1, %2};" : "=l"(d) : "f"(lo), "f"(hi))
#define UPK2(lo, hi, s) asm("mov.b64 {%0, %1}, %2;" : "=f"(lo), "=f"(hi) : "l"(s))
#define FMA2(d, a, b, c) asm("fma.rn.f32x2 %0, %1, %2, %3;" : "=l"(d) : "l"(a), "l"(b), "l"(c))
#define ADD2(d, a, b) asm("add.rn.f32x2 %0, %1, %2;" : "=l"(d) : "l"(a), "l"(b))

__device__ float g_c[2][KC][DIM];
__device__ float g_acc[KC][DIM];
__device__ float g_cnt[KC];
__device__ double g_sumx[DIM];
__device__ float g_x2[NPTS];
__device__ unsigned long long g_best[KC];
__device__ int g_seed64;
__device__ int g_tileflag[NT64];
__device__ int g_chgA[ITERS];
__device__ unsigned g_barcnt;
__device__ volatile unsigned g_bargen;
__device__ unsigned g_minx2bits;
__device__ int g_ncand;
__device__ int g_cand[CCAP];
__device__ int g_finaldone;

// ------------------------------------------------- prologue kernels

__global__ void detect_kernel(const void* __restrict__ seed) {
    __shared__ int bad;
    if (threadIdx.x == 0) {
        bad = 0;
        g_minx2bits = 0x7f7fffffu;
        g_ncand = 0;
        g_finaldone = 0;
    }
    if (threadIdx.x < DIM) g_sumx[threadIdx.x] = 0.0;
    __syncthreads();
    unsigned long long v = ((const unsigned long long*)seed)[threadIdx.x];
    if (v >= (unsigned long long)NPTS) atomicOr(&bad, 1);
    __syncthreads();
    if (threadIdx.x == 0) g_seed64 = bad ? 0 : 1;
}

__global__ void x2_kernel(const float* __restrict__ x) {
    __shared__ float wsum[8][DIM];
    const int tid = threadIdx.x;
    const int n = blockIdx.x * 256 + tid;
    const int lane = tid & 31, wid = tid >> 5;
    const bool valid = n < NPTS;
    const float4* r = (const float4*)(x + (size_t)n * DIM);

    float x2 = 0.f;
#pragma unroll
    for (int q = 0; q < 16; q++) {
        float4 v = valid ? r[q] : make_float4(0.f, 0.f, 0.f, 0.f);
        x2 = fmaf(v.x, v.x, x2); x2 = fmaf(v.y, v.y, x2);
        x2 = fmaf(v.z, v.z, x2); x2 = fmaf(v.w, v.w, x2);
#pragma unroll
        for (int off = 16; off > 0; off >>= 1) {
            v.x += __shfl_xor_sync(0xffffffffu, v.x, off);
            v.y += __shfl_xor_sync(0xffffffffu, v.y, off);
            v.z += __shfl_xor_sync(0xffffffffu, v.z, off);
            v.w += __shfl_xor_sync(0xffffffffu, v.w, off);
        }
        if (lane == 0) *(float4*)&wsum[wid][4 * q] = v;
    }
    if (valid) g_x2[n] = x2;
    if (n < NT64) g_tileflag[n] = 0;
    if (n < ITERS) g_chgA[n] = 0;
    {
        float m = valid ? x2 : 1e30f;
#pragma unroll
        for (int off = 16; off > 0; off >>= 1)
            m = fminf(m, __shfl_xor_sync(0xffffffffu, m, off));
        if (lane == 0) atomicMin(&g_minx2bits, __float_as_uint(m));
    }
    __syncthreads();
    if (tid < DIM) {
        float tot = 0.f;
#pragma unroll
        for (int w = 0; w < 8; w++) tot += wsum[w][tid];
        atomicAdd(&g_sumx[tid], (double)tot);
    }
}

__global__ void seed_kernel(const float* __restrict__ x, const void* __restrict__ seedraw) {
    int k = blockIdx.x, d = threadIdx.x;
    long long idx;
    if (g_seed64) idx = ((const long long*)seedraw)[k];
    else          idx = (long long)(((const int*)seedraw)[k]);
    g_c[0][k][d] = x[idx * DIM + d];
    g_acc[k][d] = 0.f;
    if (d == 0) { g_cnt[k] = 0.f; g_best[k] = ~0ull; }
}

__global__ void update_kernel(int it) {
    int k = blockIdx.x, d = threadIdx.x;
    double cnt = (double)NPTS - (double)g_cnt[k];
    double v = (g_sumx[d] - (double)g_acc[k][d]) / cnt;
    __syncthreads();
    g_c[(it + 1) & 1][k][d] = (float)v;
    g_acc[k][d] = 0.f;
    if (d == 0) g_cnt[k] = 0.f;
}

// ------------------------------------------- dense iteration (it=0)
// Round-14 version verbatim (best measured: 277us): 128c x 64p tiles,
// 2 CTAs/SM, prefetch pipeline, point-paired FMA2.

__global__ void __launch_bounds__(256, 2) iter_kernel(const float* __restrict__ x, int it) {
    extern __shared__ float smem[];
    float* Cs  = smem;
    float* c2s = Cs + 64 * KB;
    float* Xt  = c2s + KB;
    float* Xr  = Xt + 64 * XTI;
    float* Ms  = Xr + PBI * XRS;
    float* x2s = Ms + PBI * MSS;

    const int tid = threadIdx.x;
    const int ty = tid >> 4, tx = tid & 15;
    const int ck0 = ty * 8, p0 = tx * 4, dq = tx * 4;
    const int kb = blockIdx.y * KB;
    const int ploc = tid & 63, d0 = (tid >> 6) * 16;
    const float* cin = &g_c[it & 1][0][0];

    for (int e = tid; e < KB * DIM; e += 256) {
        int ck = e & (KB - 1), d = e >> 7;
        Cs[d * KB + ck] = cin[(size_t)(kb + ck) * DIM + d];
    }
    __syncthreads();
    if (tid < KB) {
        float s = 0.f;
#pragma unroll
        for (int d = 0; d < DIM; d++) { float c = Cs[d * KB + tid]; s = fmaf(c, c, s); }
        c2s[tid] = s;
    }
    __syncthreads();

    float c2f[8];
#pragma unroll
    for (int i = 0; i < 8; i++) c2f[i] = c2s[ck0 + i];
    u64p neg2; { float m2 = -2.0f; PK2(neg2, m2, m2); }

    u64p acc2[4][4];
#pragma unroll
    for (int i = 0; i < 4; i++)
#pragma unroll
        for (int j = 0; j < 4; j++) acc2[i][j] = 0ull;
    float cnt[8] = {0.f, 0.f, 0.f, 0.f, 0.f, 0.f, 0.f, 0.f};

    float4 pf[4];
    float pfx2 = 0.f;
    {
        const int tb = blockIdx.x * PBI;
        const float4* src = (const float4*)(x + (size_t)(tb + ploc) * DIM + d0);
#pragma unroll
        for (int k = 0; k < 4; k++) pf[k] = src[k];
        if (tid < PBI) pfx2 = g_x2[tb + tid];
    }

    for (int t = blockIdx.x; t < NTI; t += GXI) {
        __syncthreads();
        {
#pragma unroll
            for (int k = 0; k < 4; k++) {
                float4 v = pf[k];
                *(float4*)(Xr + ploc * XRS + d0 + 4 * k) = v;
                Xt[(d0 + 4 * k + 0) * XTI + ploc] = v.x;
                Xt[(d0 + 4 * k + 1) * XTI + ploc] = v.y;
                Xt[(d0 + 4 * k + 2) * XTI + ploc] = v.z;
                Xt[(d0 + 4 * k + 3) * XTI + ploc] = v.w;
            }
            if (tid < PBI) x2s[tid] = pfx2;
        }
        __syncthreads();

        const int tn = t + GXI;
        if (tn < NTI) {
            const int tbn = tn * PBI;
            const float4* src = (const float4*)(x + (size_t)(tbn + ploc) * DIM + d0);
#pragma unroll
            for (int k = 0; k < 4; k++) pf[k] = src[k];
            if (tid < PBI) pfx2 = g_x2[tbn + tid];
        }

        u64p S2[8][2];
#pragma unroll
        for (int i = 0; i < 8; i++) { S2[i][0] = 0ull; S2[i][1] = 0ull; }

#pragma unroll 8
        for (int dd = 0; dd < DIM; dd++) {
            float4 ca = *(const float4*)(Cs + dd * KB + ck0);
            float4 cb = *(const float4*)(Cs + dd * KB + ck0 + 4);
            float4 xa = *(const float4*)(Xt + dd * XTI + p0);
            u64p xp[2];
            PK2(xp[0], xa.x, xa.y); PK2(xp[1], xa.z, xa.w);
            float cv[8] = {ca.x, ca.y, ca.z, ca.w, cb.x, cb.y, cb.z, cb.w};
#pragma unroll
            for (int i = 0; i < 8; i++) {
                u64p cd; PK2(cd, cv[i], cv[i]);
                FMA2(S2[i][0], cd, xp[0], S2[i][0]);
                FMA2(S2[i][1], cd, xp[1], S2[i][1]);
            }
        }

        {
            const int sw = tx & 7;
            const int colA = 4 * ((2 * ty) ^ sw);
            const int colB = 4 * ((2 * ty + 1) ^ sw);
#pragma unroll
            for (int jp = 0; jp < 2; jp++) {
                u64p x2p; PK2(x2p, x2s[p0 + 2 * jp], x2s[p0 + 2 * jp + 1]);
                float mlo[8], mhi[8];
#pragma unroll
                for (int i = 0; i < 8; i++) {
                    u64p c2d; PK2(c2d, c2f[i], c2f[i]);
                    u64p tsum; ADD2(tsum, c2d, x2p);
                    u64p d2;   FMA2(d2, neg2, S2[i][jp], tsum);
                    float dlo, dhi; UPK2(dlo, dhi, d2);
                    mlo[i] = (dlo < BW2) ? 0.f : 1.f;
                    mhi[i] = (dhi < BW2) ? 0.f : 1.f;
                    cnt[i] += mlo[i] + mhi[i];
                }
                int pA = p0 + 2 * jp, pB = pA + 1;
                *(float4*)(Ms + pA * MSS + colA) = make_float4(mlo[0], mlo[1], mlo[2], mlo[3]);
                *(float4*)(Ms + pA * MSS + colB) = make_float4(mlo[4], mlo[5], mlo[6], mlo[7]);
                *(float4*)(Ms + pB * MSS + colA) = make_float4(mhi[0], mhi[1], mhi[2], mhi[3]);
                *(float4*)(Ms + pB * MSS + colB) = make_float4(mhi[4], mhi[5], mhi[6], mhi[7]);
            }
        }
        __syncthreads();

#pragma unroll 4
        for (int p = 0; p < PBI; p++) {
            const int sw2 = (p >> 2) & 7;
            float4 ma = *(const float4*)(Ms + p * MSS + 4 * ((2 * ty) ^ sw2));
            float4 mb = *(const float4*)(Ms + p * MSS + 4 * ((2 * ty + 1) ^ sw2));
            float4 xv = *(const float4*)(Xr + p * XRS + dq);
            u64p mp[4];
            PK2(mp[0], ma.x, ma.y); PK2(mp[1], ma.z, ma.w);
            PK2(mp[2], mb.x, mb.y); PK2(mp[3], mb.z, mb.w);
            u64p xd[4];
            PK2(xd[0], xv.x, xv.x); PK2(xd[1], xv.y, xv.y);
            PK2(xd[2], xv.z, xv.z); PK2(xd[3], xv.w, xv.w);
#pragma unroll
            for (int i2 = 0; i2 < 4; i2++)
#pragma unroll
                for (int j = 0; j < 4; j++) FMA2(acc2[i2][j], mp[i2], xd[j], acc2[i2][j]);
        }
    }

#pragma unroll
    for (int i2 = 0; i2 < 4; i2++)
#pragma unroll
        for (int j = 0; j < 4; j++) {
            float alo, ahi; UPK2(alo, ahi, acc2[i2][j]);
            atomicAdd(&g_acc[kb + ck0 + 2 * i2 + 0][dq + j], alo);
            atomicAdd(&g_acc[kb + ck0 + 2 * i2 + 1][dq + j], ahi);
        }
#pragma unroll
    for (int i = 0; i < 8; i++) {
        float v = cnt[i];
#pragma unroll
        for (int off = 8; off > 0; off >>= 1)
            v += __shfl_down_sync(0xffffffffu, v, off, 16);
        if (tx == 0) atomicAdd(&g_cnt[kb + ck0 + i], v);
    }
}

// ------------------------------------------- persistent sparse iterations 1..9
// + fused sparse final argmin (round-14 version).

static __device__ __forceinline__ void grid_sync() {
    __threadfence();
    __syncthreads();
    if (threadIdx.x == 0) {
        unsigned gen = g_bargen;
        if (atomicAdd(&g_barcnt, 1u) == SPB - 1) {
            g_barcnt = 0;
            __threadfence();
            g_bargen = gen + 1;
        } else {
            while (g_bargen == gen) { __nanosleep(32); }
        }
    }
    __syncthreads();
}

__global__ void __launch_bounds__(256) sparse_all(const float* __restrict__ x) {
    __shared__ float red[KC];
    __shared__ float redB[KC];
    __shared__ unsigned long long rmin[256];
    const int tid = threadIdx.x;
    const int gtid = blockIdx.x * 256 + tid;
    const int stride = SPB * 256;

    for (int it = 1; it < ITERS; it++) {
        const float* cc = &g_c[it & 1][0][0];
        {
            const float4* cr = (const float4*)(cc + (size_t)tid * DIM);
            float c2 = 0.f;
#pragma unroll
            for (int q = 0; q < 16; q++) {
                float4 v = cr[q];
                c2 = fmaf(v.x, v.x, c2); c2 = fmaf(v.y, v.y, c2);
                c2 = fmaf(v.z, v.z, c2); c2 = fmaf(v.w, v.w, c2);
            }
            red[tid] = c2;
            __syncthreads();
            for (int s = 128; s > 0; s >>= 1) {
                if (tid < s) red[tid] = fmaxf(red[tid], red[tid + s]);
                __syncthreads();
            }
        }
        const float cmax = sqrtf(red[0]) + 1e-3f;
        __syncthreads();
        float tthr = 12.0f - cmax - 1e-3f;
        const float thr2 = (tthr > 0.f) ? tthr * tthr : -1.0f;

        for (int n = gtid; n < NPTS; n += stride) {
            const float x2 = g_x2[n];
            if (x2 < thr2) continue;
            g_tileflag[n >> 6] = 1;

            float xv[DIM];
            const float4* xr = (const float4*)(x + (size_t)n * DIM);
#pragma unroll
            for (int q = 0; q < 16; q++) {
                float4 v = xr[q];
                xv[4 * q + 0] = v.x; xv[4 * q + 1] = v.y;
                xv[4 * q + 2] = v.z; xv[4 * q + 3] = v.w;
            }
            for (int k = 0; k < KC; k++) {
                const float4* cr = (const float4*)(cc + (size_t)k * DIM);
                float dot = 0.f, c2 = 0.f;
#pragma unroll
                for (int q = 0; q < 16; q++) {
                    float4 cv = cr[q];
                    dot = fmaf(cv.x, xv[4 * q + 0], dot);
                    dot = fmaf(cv.y, xv[4 * q + 1], dot);
                    dot = fmaf(cv.z, xv[4 * q + 2], dot);
                    dot = fmaf(cv.w, xv[4 * q + 3], dot);
                    c2 = fmaf(cv.x, cv.x, c2); c2 = fmaf(cv.y, cv.y, c2);
                    c2 = fmaf(cv.z, cv.z, c2); c2 = fmaf(cv.w, cv.w, c2);
                }
                float d2 = c2 + x2 - 2.f * dot;
                if (!(d2 < BW2)) {
                    atomicAdd(&g_cnt[k], 1.0f);
#pragma unroll
                    for (int d = 0; d < DIM; d++) atomicAdd(&g_acc[k][d], xv[d]);
                }
            }
        }

        grid_sync();

        int diff = 0;
        {
            int k = -1, d = tid & 63;
            if (tid < 64) k = blockIdx.x;
            else if (tid < 128) { int kk = blockIdx.x + SPB; if (kk < KC) k = kk; }
            if (k >= 0) {
                double cnt = (double)NPTS - (double)g_cnt[k];
                double v = (g_sumx[d] - (double)g_acc[k][d]) / cnt;
                float nf = (float)v;
                if (__float_as_uint(nf) != __float_as_uint(g_c[it & 1][k][d])) diff = 1;
                g_c[(it + 1) & 1][k][d] = nf;
                g_acc[k][d] = 0.f;
            }
        }
        if (__syncthreads_or(diff) && tid == 0) atomicOr(&g_chgA[it], 1);
        if (tid == 0) {
            g_cnt[blockIdx.x] = 0.f;
            int kk = blockIdx.x + SPB;
            if (kk < KC) g_cnt[kk] = 0.f;
        }

        grid_sync();

        if (g_chgA[it] == 0) break;
    }

    // ---- fused sparse final argmin ----
    {
        const float4* ca = (const float4*)&g_c[0][tid][0];
        const float4* cb = (const float4*)&g_c[1][tid][0];
        float c2a = 0.f, c2b = 0.f;
#pragma unroll
        for (int q = 0; q < 16; q++) {
            float4 va = ca[q], vb = cb[q];
            c2a = fmaf(va.x, va.x, c2a); c2a = fmaf(va.y, va.y, c2a);
            c2a = fmaf(va.z, va.z, c2a); c2a = fmaf(va.w, va.w, c2a);
            c2b = fmaf(vb.x, vb.x, c2b); c2b = fmaf(vb.y, vb.y, c2b);
            c2b = fmaf(vb.z, vb.z, c2b); c2b = fmaf(vb.w, vb.w, c2b);
        }
        red[tid] = c2a; redB[tid] = c2b;
        __syncthreads();
        for (int s = 128; s > 0; s >>= 1) {
            if (tid < s) {
                red[tid] = fmaxf(red[tid], red[tid + s]);
                redB[tid] = fmaxf(redB[tid], redB[tid + s]);
            }
            __syncthreads();
        }
    }
    const float cmax10 = sqrtf(red[0]) + 1e-3f;
    const float cmax9  = sqrtf(redB[0]) + 1e-3f;
    const float minx   = sqrtf(__uint_as_float(g_minx2bits));
    const float thr    = minx + 2.f * cmax10 + 0.05f;
    const float thr2   = thr * thr;
    const bool valid   = (minx + cmax9 + 0.05f < 12.0f);

    if (valid) {
        for (int n = gtid; n < NPTS; n += stride) {
            if (g_x2[n] <= thr2) {
                int pos = atomicAdd(&g_ncand, 1);
                if (pos < CCAP) g_cand[pos] = n;
            }
        }
    }
    grid_sync();
    const int ncand = g_ncand;
    if (!valid || ncand == 0 || ncand > CCAP) return;

    for (int k = blockIdx.x; k < KC; k += SPB) {
        unsigned long long bk = ~0ull;
        for (int j = tid; j < ncand; j += 256) {
            const int n = g_cand[j];
            const float* xr = x + (size_t)n * DIM;
            const float x2 = g_x2[n];
            const float* c9r  = &g_c[1][k][0];
            const float* c10r = &g_c[0][k][0];
            float dot9 = 0.f, dot10 = 0.f, c29 = 0.f, c210 = 0.f;
            for (int d = 0; d < DIM; d++) {
                float xv = xr[d], v9 = c9r[d], v10 = c10r[d];
                dot9  = fmaf(v9,  xv, dot9);
                dot10 = fmaf(v10, xv, dot10);
                c29   = fmaf(v9,  v9,  c29);
                c210  = fmaf(v10, v10, c210);
            }
            float d9 = fmaf(-2.f, dot9, c29 + x2);
            if (d9 < BW2) {
                float d2 = fmaxf(fmaf(-2.f, dot10, c210 + x2), 0.f);
                unsigned long long key =
                    ((unsigned long long)__float_as_uint(d2) << 32) | (unsigned)n;
                if (key < bk) bk = key;
            }
        }
        rmin[tid] = bk;
        __syncthreads();
        for (int s = 128; s > 0; s >>= 1) {
            if (tid < s && rmin[tid + s] < rmin[tid]) rmin[tid] = rmin[tid + s];
            __syncthreads();
        }
        if (tid == 0 && rmin[0] != ~0ull) atomicMin(&g_best[k], rmin[0]);
        __syncthreads();
    }
    if (blockIdx.x == 0 && tid == 0) g_finaldone = 1;
}

// ------------------------------------------- dense final (fallback only)

__global__ void __launch_bounds__(256, 2) final_kernel(const float* __restrict__ x) {
    if (g_finaldone) return;
    extern __shared__ float sm[];
    float* Ct   = sm;
    float* c210 = Ct + 64 * KB;
    float* Xt   = c210 + KB;
    float* x2s  = Xt + 64 * XTS;

    const int tid = threadIdx.x;
    const int ty = tid >> 4, tx = tid & 15;
    const int ck0 = ty * 8, p0 = tx * 8;
    const int kb = blockIdx.y * KB;

    for (int e = tid; e < KB * DIM; e += 256) {
        int ck = e & (KB - 1), d = e >> 7;
        Ct[d * KB + ck] = g_c[0][kb + ck][d];
    }
    __syncthreads();
    if (tid < KB) {
        float s = 0.f;
#pragma unroll
        for (int d = 0; d < DIM; d++) { float a = Ct[d * KB + tid]; s = fmaf(a, a, s); }
        c210[tid] = s;
    }
    __syncthreads();

    unsigned long long best[8];
#pragma unroll
    for (int i = 0; i < 8; i++) best[i] = ~0ull;

    for (int t = blockIdx.x; t < NT128; t += GXF) {
        const int tb = t * PB;
        __syncthreads();
        {
            int ploc = tid & 127, d0 = (tid >> 7) * 32;
            bool valid = (tb + ploc) < NPTS;
            const float4* src = (const float4*)(x + (size_t)(tb + ploc) * DIM + d0);
#pragma unroll
            for (int k = 0; k < 8; k++) {
                float4 v = valid ? src[k] : make_float4(0.f, 0.f, 0.f, 0.f);
                Xt[(d0 + 4 * k + 0) * XTS + ploc] = v.x;
                Xt[(d0 + 4 * k + 1) * XTS + ploc] = v.y;
                Xt[(d0 + 4 * k + 2) * XTS + ploc] = v.z;
                Xt[(d0 + 4 * k + 3) * XTS + ploc] = v.w;
            }
            if (tid < PB) x2s[tid] = ((tb + tid) < NPTS) ? g_x2[tb + tid] : 0.f;
        }
        __syncthreads();

        u64p S2[8][4];
#pragma unroll
        for (int i = 0; i < 8; i++)
#pragma unroll
            for (int j = 0; j < 4; j++) S2[i][j] = 0ull;

#pragma unroll 8
        for (int dd = 0; dd < DIM; dd++) {
            float4 ca = *(const float4*)(Ct + dd * KB + ck0);
            float4 cb = *(const float4*)(Ct + dd * KB + ck0 + 4);
            float4 xa = *(const float4*)(Xt + dd * XTS + p0);
            float4 xb = *(const float4*)(Xt + dd * XTS + p0 + 4);
            u64p xp[4];
            PK2(xp[0], xa.x, xa.y); PK2(xp[1], xa.z, xa.w);
            PK2(xp[2], xb.x, xb.y); PK2(xp[3], xb.z, xb.w);
            float cv[8] = {ca.x, ca.y, ca.z, ca.w, cb.x, cb.y, cb.z, cb.w};
#pragma unroll
            for (int i = 0; i < 8; i++) {
                u64p cd; PK2(cd, cv[i], cv[i]);
#pragma unroll
                for (int j = 0; j < 4; j++) FMA2(S2[i][j], cd, xp[j], S2[i][j]);
            }
        }

        const int flagged = g_tileflag[2 * t] |
                            ((2 * t + 1 < NT64) ? g_tileflag[2 * t + 1] : 0);

#pragma unroll
        for (int jp = 0; jp < 4; jp++) {
            const int pA = p0 + 2 * jp, pB = pA + 1;
            const float xa2 = x2s[pA], xb2 = x2s[pB];
            const unsigned ia = (unsigned)(tb + pA), ib = (unsigned)(tb + pB);
#pragma unroll
            for (int i = 0; i < 8; i++) {
                float dlo, dhi; UPK2(dlo, dhi, S2[i][jp]);
                const float c2v = c210[ck0 + i];
                bool oka = true, okb = true;
                if (flagged) {
                    const float* c9r = &g_c[1][kb + ck0 + i][0];
                    float d9a = 0.f, d9b = 0.f, c29v = 0.f;
                    for (int dd = 0; dd < DIM; dd++) {
                        float cv9 = c9r[dd];
                        d9a = fmaf(cv9, Xt[dd * XTS + pA], d9a);
                        d9b = fmaf(cv9, Xt[dd * XTS + pB], d9b);
                        c29v = fmaf(cv9, cv9, c29v);
                    }
                    oka = fmaf(-2.f, d9a, c29v + xa2) < BW2;
                    okb = fmaf(-2.f, d9b, c29v + xb2) < BW2;
                }
                if (oka && ia < NPTS) {
                    float d2 = fmaxf(fmaf(-2.f, dlo, c2v + xa2), 0.f);
                    unsigned long long key =
                        ((unsigned long long)__float_as_uint(d2) << 32) | ia;
                    if (key < best[i]) best[i] = key;
                }
                if (okb && ib < NPTS) {
                    float d2 = fmaxf(fmaf(-2.f, dhi, c2v + xb2), 0.f);
                    unsigned long long key =
                        ((unsigned long long)__float_as_uint(d2) << 32) | ib;
                    if (key < best[i]) best[i] = key;
                }
            }
        }
    }

#pragma unroll
    for (int i = 0; i < 8; i++) {
        unsigned long long v = best[i];
#pragma unroll
        for (int off = 8; off > 0; off >>= 1) {
            unsigned long long o = __shfl_down_sync(0xffffffffu, v, off, 16);
            if (o < v) v = o;
        }
        if (tx == 0) atomicMin(&g_best[kb + ck0 + i], v);
    }
}

// ---------------------------------------------------------------- epilogue

__global__ void zero_out(float* out, int n) {
    int i = blockIdx.x * blockDim.x + threadIdx.x;
    if (i < n) out[i] = 0.f;
}

__global__ void finish_kernel(float* __restrict__ out, const float* __restrict__ x,
                              int out_size) {
    int k = blockIdx.x, d = threadIdx.x;
    if (out_size >= KC * DIM)
        out[k * DIM + d] = g_c[0][k][d];
    unsigned long long b = g_best[k];
    unsigned idx = (b == ~0ull) ? 0u : (unsigned)(b & 0xffffffffu);
    if (out_size >= 2 * KC * DIM)
        out[KC * DIM + k * DIM + d] = x[(size_t)idx * DIM + d];
    if (d == 0 && out_size >= 2 * KC * DIM + KC)
        out[2 * KC * DIM + k] = (float)idx;
}

// ---------------------------------------------------------------- launcher

extern "C" void kernel_launch(void* const* d_in, const int* in_sizes, int n_in,
                              void* d_out, int out_size) {
    const float* x = (const float*)d_in[0];
    const void* seed = d_in[1];
    float* out = (float*)d_out;
    (void)in_sizes; (void)n_in;

    const size_t iterSmem = (size_t)(64 * KB + KB + 64 * XTI + PBI * XRS + PBI * MSS + PBI)
                            * sizeof(float);
    const size_t finalSmem = (size_t)(64 * KB + KB + 64 * XTS + PB) * sizeof(float);
    cudaFuncSetAttribute(iter_kernel,  cudaFuncAttributeMaxDynamicSharedMemorySize, (int)iterSmem);
    cudaFuncSetAttribute(final_kernel, cudaFuncAttributeMaxDynamicSharedMemorySize, (int)finalSmem);

    detect_kernel<<<1, 128>>>(seed);
    x2_kernel<<<(NPTS + 255) / 256, 256>>>(x);
    seed_kernel<<<KC, DIM>>>(x, seed);

    iter_kernel<<<dim3(GXI, KC / KB), 256, iterSmem>>>(x, 0);
    update_kernel<<<KC, DIM>>>(0);

    sparse_all<<<SPB, 256>>>(x);     // iterations 1..9 + sparse final argmin

    final_kernel<<<dim3(GXF, KC / KB), 256, finalSmem>>>(x);   // fallback

    // finish_kernel writes every output element when out_size == 33024
    if (out_size > 0 && out_size != 2 * KC * DIM + KC)
        zero_out<<<(out_size + 255) / 256, 256>>>(out, out_size);
    finish_kernel<<<KC, DIM>>>(out, x, out_size);
}